// round 4
// baseline (speedup 1.0000x reference)
#include <cuda_runtime.h>
#include <cstdint>

#define N_NODES 50000
#define IN_FEAT 512
#define OUT_FEAT 256
#define N_EDGES 1600000
#define ALPHA 0.2f

// Scratch (allocation-free rule: __device__ globals).
// float4 arrays so 128-bit accesses are legally aligned.
__device__ float4 g_w_src4[IN_FEAT / 4];
__device__ float4 g_w_tgt4[IN_FEAT / 4];
__device__ float g_s_src[N_NODES];
__device__ float g_s_tgt[N_NODES];

__device__ __forceinline__ float dot4(float4 a, float4 b) {
    return a.x * b.x + a.y * b.y + a.z * b.z + a.w * b.w;
}

// ---------------------------------------------------------------------------
// Kernel A: w_src = W @ a_src, w_tgt = W @ a_tgt.  One warp per row of W.
// W is [IN_FEAT, OUT_FEAT] row-major, attn_w is [2*OUT_FEAT].
// float4-vectorized: 64 float4 per row -> 2 per lane.
// ---------------------------------------------------------------------------
__global__ void compute_w_kernel(const float* __restrict__ W,
                                 const float* __restrict__ attn_w) {
    int warp = (blockIdx.x * blockDim.x + threadIdx.x) >> 5;
    int lane = threadIdx.x & 31;
    if (warp >= IN_FEAT) return;

    const float4* wrow4 = reinterpret_cast<const float4*>(W + (size_t)warp * OUT_FEAT);
    const float4* as4   = reinterpret_cast<const float4*>(attn_w);             // 64 float4
    const float4* at4   = reinterpret_cast<const float4*>(attn_w + OUT_FEAT);  // 64 float4

    float4 w0 = wrow4[lane];
    float4 w1 = wrow4[32 + lane];
    float acc_s = dot4(w0, as4[lane]) + dot4(w1, as4[32 + lane]);
    float acc_t = dot4(w0, at4[lane]) + dot4(w1, at4[32 + lane]);

#pragma unroll
    for (int off = 16; off > 0; off >>= 1) {
        acc_s += __shfl_xor_sync(0xffffffffu, acc_s, off);
        acc_t += __shfl_xor_sync(0xffffffffu, acc_t, off);
    }
    if (lane == 0) {
        reinterpret_cast<float*>(g_w_src4)[warp] = acc_s;
        reinterpret_cast<float*>(g_w_tgt4)[warp] = acc_t;
    }
}

// ---------------------------------------------------------------------------
// Kernel B: per-node scores, grid-stride warps with w held in registers.
// Each lane owns float4 slots {lane, 32+lane, 64+lane, 96+lane} of the
// 128-float4 w vectors -> 8 float4 registers, loaded once, reused per node.
// ---------------------------------------------------------------------------
#define B_BLOCKS 592          // 148 SMs * 4 blocks: exactly one wave
#define B_THREADS 256

__global__ __launch_bounds__(B_THREADS) void node_scores_kernel(const float* __restrict__ h) {
    int lane = threadIdx.x & 31;

    float4 ws[4], wt[4];
#pragma unroll
    for (int i = 0; i < 4; i++) {
        ws[i] = g_w_src4[i * 32 + lane];
        wt[i] = g_w_tgt4[i * 32 + lane];
    }

    int warp_global = (blockIdx.x * blockDim.x + threadIdx.x) >> 5;
    const int n_warps = (B_BLOCKS * B_THREADS) >> 5;

    for (int node = warp_global; node < N_NODES; node += n_warps) {
        const float4* h4 = reinterpret_cast<const float4*>(h + (size_t)node * IN_FEAT);

        float4 hv0 = h4[lane];
        float4 hv1 = h4[32 + lane];
        float4 hv2 = h4[64 + lane];
        float4 hv3 = h4[96 + lane];

        float acc_s = dot4(hv0, ws[0]) + dot4(hv1, ws[1]) +
                      dot4(hv2, ws[2]) + dot4(hv3, ws[3]);
        float acc_t = dot4(hv0, wt[0]) + dot4(hv1, wt[1]) +
                      dot4(hv2, wt[2]) + dot4(hv3, wt[3]);

#pragma unroll
        for (int off = 16; off > 0; off >>= 1) {
            acc_s += __shfl_xor_sync(0xffffffffu, acc_s, off);
            acc_t += __shfl_xor_sync(0xffffffffu, acc_t, off);
        }
        if (lane == 0) {
            g_s_src[node] = acc_s;
            g_s_tgt[node] = acc_t;
        }
    }
}

// ---------------------------------------------------------------------------
// Kernel C: per-edge gather + leaky_relu, 4 edges per thread (int4/float4).
// edge_list is [2, N_EDGES] int32: row 0 = source, row 1 = target.
// ---------------------------------------------------------------------------
__global__ void edge_kernel(const int* __restrict__ edge_list,
                            float* __restrict__ out) {
    int k4 = blockIdx.x * blockDim.x + threadIdx.x;
    if (k4 >= N_EDGES / 4) return;

    int4 s = reinterpret_cast<const int4*>(edge_list)[k4];
    int4 t = reinterpret_cast<const int4*>(edge_list + N_EDGES)[k4];

    float e0 = __ldg(&g_s_src[s.x]) + __ldg(&g_s_tgt[t.x]);
    float e1 = __ldg(&g_s_src[s.y]) + __ldg(&g_s_tgt[t.y]);
    float e2 = __ldg(&g_s_src[s.z]) + __ldg(&g_s_tgt[t.z]);
    float e3 = __ldg(&g_s_src[s.w]) + __ldg(&g_s_tgt[t.w]);

    float4 r;
    r.x = (e0 > 0.f) ? e0 : ALPHA * e0;
    r.y = (e1 > 0.f) ? e1 : ALPHA * e1;
    r.z = (e2 > 0.f) ? e2 : ALPHA * e2;
    r.w = (e3 > 0.f) ? e3 : ALPHA * e3;
    reinterpret_cast<float4*>(out)[k4] = r;
}

// ---------------------------------------------------------------------------
extern "C" void kernel_launch(void* const* d_in, const int* in_sizes, int n_in,
                              void* d_out, int out_size) {
    const float* h         = (const float*)d_in[0];
    const int*   edge_list = (const int*)d_in[1];
    const float* W         = (const float*)d_in[2];
    const float* attn_w    = (const float*)d_in[3];
    float* out = (float*)d_out;

    // A: 512 warps -> 64 blocks x 256 threads
    compute_w_kernel<<<64, 256>>>(W, attn_w);

    // B: one full wave of persistent-ish warps, w in registers
    node_scores_kernel<<<B_BLOCKS, B_THREADS>>>(h);

    // C: 4 edges per thread
    edge_kernel<<<(N_EDGES / 4 + 255) / 256, 256>>>(edge_list, out);
}

// round 5
// speedup vs baseline: 1.0453x; 1.0453x over previous
#include <cuda_runtime.h>
#include <cstdint>

#define N_NODES 50000
#define IN_FEAT 512
#define OUT_FEAT 256
#define N_EDGES 1600000
#define ALPHA 0.2f

// Scratch (allocation-free rule: __device__ globals).
__device__ float4 g_w_src4[IN_FEAT / 4];
__device__ float4 g_w_tgt4[IN_FEAT / 4];
__device__ float g_s_src[N_NODES];
__device__ float g_s_tgt[N_NODES];

// Monotonic grid barrier counter. Never reset: each barrier consumes exactly
// `nblocks` tickets, so a block's release target is the next multiple of
// nblocks above its own ticket. Works across graph replays (counter keeps
// growing; wraps after ~4B arrivals which is far beyond any timing run).
__device__ unsigned g_bar = 0;

__device__ __forceinline__ float dot4(float4 a, float4 b) {
    return a.x * b.x + a.y * b.y + a.z * b.z + a.w * b.w;
}

__device__ __forceinline__ void grid_sync(unsigned nblocks) {
    __syncthreads();
    if (threadIdx.x == 0) {
        __threadfence();                                  // release prior writes
        unsigned ticket = atomicAdd(&g_bar, 1u);
        unsigned target = (ticket / nblocks + 1u) * nblocks;
        while (*(volatile unsigned*)&g_bar < target) { }  // spin (L2 read)
        __threadfence();                                  // acquire
    }
    __syncthreads();
}

// ---------------------------------------------------------------------------
// Fused persistent kernel: phase A (W projection) -> barrier ->
// phase B (node scores) -> barrier -> phase C (edge gather + leaky_relu).
// ---------------------------------------------------------------------------
__global__ __launch_bounds__(256, 4) void fused_gat_kernel(
    const float* __restrict__ h,
    const int*   __restrict__ edge_list,
    const float* __restrict__ W,
    const float* __restrict__ attn_w,
    float*       __restrict__ out,
    int nblocks)
{
    const int tid  = threadIdx.x;
    const int lane = tid & 31;
    const int wid  = tid >> 5;
    const int gw   = blockIdx.x * 8 + wid;      // global warp id
    const int nwarps   = nblocks * 8;
    const int nthreads = nblocks * 256;

    // ---------------- Phase A: w_src = W @ a_src, w_tgt = W @ a_tgt --------
    // One warp per row of W (first 512 warps). W row-major [IN_FEAT, OUT_FEAT].
    if (gw < IN_FEAT) {
        const float4* wrow4 = reinterpret_cast<const float4*>(W + (size_t)gw * OUT_FEAT);
        const float4* as4   = reinterpret_cast<const float4*>(attn_w);
        const float4* at4   = reinterpret_cast<const float4*>(attn_w + OUT_FEAT);

        float4 w0 = wrow4[lane];
        float4 w1 = wrow4[32 + lane];
        float acc_s = dot4(w0, as4[lane]) + dot4(w1, as4[32 + lane]);
        float acc_t = dot4(w0, at4[lane]) + dot4(w1, at4[32 + lane]);
#pragma unroll
        for (int off = 16; off > 0; off >>= 1) {
            acc_s += __shfl_xor_sync(0xffffffffu, acc_s, off);
            acc_t += __shfl_xor_sync(0xffffffffu, acc_t, off);
        }
        if (lane == 0) {
            reinterpret_cast<float*>(g_w_src4)[gw] = acc_s;
            reinterpret_cast<float*>(g_w_tgt4)[gw] = acc_t;
        }
    }

    grid_sync(nblocks);

    // Stage w vectors into shared (4 KB, L2-hot after phase A)
    __shared__ float4 sh_ws[IN_FEAT / 4];
    __shared__ float4 sh_wt[IN_FEAT / 4];
    for (int i = tid; i < IN_FEAT / 4; i += 256) {
        sh_ws[i] = g_w_src4[i];
        sh_wt[i] = g_w_tgt4[i];
    }
    __syncthreads();

    // ---------------- Phase B: node scores (warp per node, grid-stride) ----
    for (int node = gw; node < N_NODES; node += nwarps) {
        const float4* h4 = reinterpret_cast<const float4*>(h + (size_t)node * IN_FEAT);

        float4 hv0 = h4[lane];
        float4 hv1 = h4[32 + lane];
        float4 hv2 = h4[64 + lane];
        float4 hv3 = h4[96 + lane];

        float acc_s = dot4(hv0, sh_ws[lane])      + dot4(hv1, sh_ws[32 + lane]) +
                      dot4(hv2, sh_ws[64 + lane]) + dot4(hv3, sh_ws[96 + lane]);
        float acc_t = dot4(hv0, sh_wt[lane])      + dot4(hv1, sh_wt[32 + lane]) +
                      dot4(hv2, sh_wt[64 + lane]) + dot4(hv3, sh_wt[96 + lane]);
#pragma unroll
        for (int off = 16; off > 0; off >>= 1) {
            acc_s += __shfl_xor_sync(0xffffffffu, acc_s, off);
            acc_t += __shfl_xor_sync(0xffffffffu, acc_t, off);
        }
        if (lane == 0) {
            g_s_src[node] = acc_s;
            g_s_tgt[node] = acc_t;
        }
    }

    grid_sync(nblocks);

    // ---------------- Phase C: edge gather + leaky_relu (4 edges/thread) ---
    const int n4 = N_EDGES / 4;
    const int4*  src4 = reinterpret_cast<const int4*>(edge_list);
    const int4*  tgt4 = reinterpret_cast<const int4*>(edge_list + N_EDGES);
    float4*      out4 = reinterpret_cast<float4*>(out);

    for (int k4 = blockIdx.x * 256 + tid; k4 < n4; k4 += nthreads) {
        int4 s = src4[k4];
        int4 t = tgt4[k4];

        float e0 = __ldg(&g_s_src[s.x]) + __ldg(&g_s_tgt[t.x]);
        float e1 = __ldg(&g_s_src[s.y]) + __ldg(&g_s_tgt[t.y]);
        float e2 = __ldg(&g_s_src[s.z]) + __ldg(&g_s_tgt[t.z]);
        float e3 = __ldg(&g_s_src[s.w]) + __ldg(&g_s_tgt[t.w]);

        float4 r;
        r.x = (e0 > 0.f) ? e0 : ALPHA * e0;
        r.y = (e1 > 0.f) ? e1 : ALPHA * e1;
        r.z = (e2 > 0.f) ? e2 : ALPHA * e2;
        r.w = (e3 > 0.f) ? e3 : ALPHA * e3;
        out4[k4] = r;
    }
}

// ---------------------------------------------------------------------------
extern "C" void kernel_launch(void* const* d_in, const int* in_sizes, int n_in,
                              void* d_out, int out_size) {
    const float* h         = (const float*)d_in[0];
    const int*   edge_list = (const int*)d_in[1];
    const float* W         = (const float*)d_in[2];
    const float* attn_w    = (const float*)d_in[3];
    float* out = (float*)d_out;

    // Size grid to exactly one co-resident wave (required by the grid barrier).
    // Pure queries — capture-safe, deterministic, no allocation.
    int dev = 0;
    cudaGetDevice(&dev);
    int sms = 148;
    cudaDeviceGetAttribute(&sms, cudaDevAttrMultiProcessorCount, dev);
    int occ = 1;
    cudaOccupancyMaxActiveBlocksPerMultiprocessor(&occ, fused_gat_kernel, 256, 0);
    if (occ < 1) occ = 1;
    int nblocks = sms * occ;
    // Need at least 512 warps for phase A's one-warp-per-row mapping.
    if (nblocks < 64) nblocks = 64;

    fused_gat_kernel<<<nblocks, 256>>>(h, edge_list, W, attn_w, out, nblocks);
}